// round 1
// baseline (speedup 1.0000x reference)
#include <cuda_runtime.h>

// PixelWiseRNN: h_t = tanh(w_ih*x_t + b_ih + w_hh*h_{t-1} + b_hh), h_0 = 0
// x: (B, T, Z, H, W) fp32, params: (Z, H, W) fp32, out: (B, T, Z, H, W) fp32
// B=4, T=256, Z=16, H=64, W=64  ->  P = Z*H*W = 65536 pixels per batch.

#define RNN_B 4
#define RNN_T 256
#define RNN_P 65536   // Z*H*W

__global__ __launch_bounds__(256) void pixel_rnn_kernel(
    const float* __restrict__ x,
    const float* __restrict__ w_ih,
    const float* __restrict__ w_hh,
    const float* __restrict__ b_ih,
    const float* __restrict__ b_hh,
    float* __restrict__ out)
{
    const int gid = blockIdx.x * blockDim.x + threadIdx.x;   // [0, B*P)
    const int b = gid >> 16;          // gid / P
    const int p = gid & (RNN_P - 1);  // gid % P

    const float wi   = w_ih[p];
    const float wh   = w_hh[p];
    const float bias = b_ih[p] + b_hh[p];

    const size_t base = (size_t)b * RNN_T * RNN_P + p;
    const float* __restrict__ xp = x + base;
    float* __restrict__ op = out + base;

    float h  = 0.0f;
    float xv = xp[0];   // prefetched x_0

    #pragma unroll 4
    for (int t = 0; t < RNN_T; t++) {
        // Prefetch next x off the dependency chain (clamped at the end).
        const int tn = (t + 1 < RNN_T) ? (t + 1) : t;
        const float xn = xp[(size_t)tn * RNN_P];

        // Off-chain part first: a = wi*x + bias (independent of h).
        const float a = fmaf(wi, xv, bias);
        h = tanhf(fmaf(wh, h, a));

        op[(size_t)t * RNN_P] = h;
        xv = xn;
    }
}

extern "C" void kernel_launch(void* const* d_in, const int* in_sizes, int n_in,
                              void* d_out, int out_size)
{
    const float* x    = (const float*)d_in[0];
    const float* w_ih = (const float*)d_in[1];
    const float* w_hh = (const float*)d_in[2];
    const float* b_ih = (const float*)d_in[3];
    const float* b_hh = (const float*)d_in[4];
    float* out = (float*)d_out;

    const int total_threads = RNN_B * RNN_P;   // 262144
    const int block = 256;
    const int grid = total_threads / block;    // 1024

    pixel_rnn_kernel<<<grid, block>>>(x, w_ih, w_hh, b_ih, b_hh, out);
}